// round 14
// baseline (speedup 1.0000x reference)
#include <cuda_runtime.h>
#include <mma.h>
#include <cuda_fp16.h>
#include <math.h>
#include <stdint.h>

using namespace nvcuda;

#define B_   2
#define S_   2048
#define D_   1024
#define H_   16
#define DK_  64
#define MTOT (B_ * S_)   // 4096
#define LOG2E 1.44269504088896340736f

__device__ __half g_qh[MTOT * D_];
__device__ __half g_kh[MTOT * D_];
__device__ __half g_vh[MTOT * D_];
__device__ __half g_Wh[4 * D_ * D_];    // transposed weights [N,K], fp16
__device__ __half g_Qh[MTOT * D_];      // projected Q (rope, x 0.125*log2e)
__device__ __half g_Kh[MTOT * D_];      // projected K (rope)
__device__ __half g_Vh[MTOT * D_];      // projected V
__device__ __half g_Ath[MTOT * D_];     // attention output
__device__ float  g_cos[S_ * 32];
__device__ float  g_sin[S_ * 32];

__device__ __forceinline__ uint32_t smem_u32(const void* p) {
    uint32_t a;
    asm("{ .reg .u64 t; cvta.to.shared.u64 t, %1; cvt.u32.u64 %0, t; }" : "=r"(a) : "l"(p));
    return a;
}
__device__ __forceinline__ void cpa16(uint32_t dst, const void* src) {
    asm volatile("cp.async.cg.shared.global [%0], [%1], 16;" :: "r"(dst), "l"(src) : "memory");
}
#define CPA_COMMIT() asm volatile("cp.async.commit_group;" ::: "memory")
#define CPA_WAIT1()  asm volatile("cp.async.wait_group 1;" ::: "memory")
#define CPA_WAIT0()  asm volatile("cp.async.wait_group 0;" ::: "memory")

__device__ __forceinline__ void mma16816(float* c, const uint32_t* a, const uint32_t* b) {
    asm volatile("mma.sync.aligned.m16n8k16.row.col.f32.f16.f16.f32 "
        "{%0,%1,%2,%3}, {%4,%5,%6,%7}, {%8,%9}, {%0,%1,%2,%3};"
        : "+f"(c[0]), "+f"(c[1]), "+f"(c[2]), "+f"(c[3])
        : "r"(a[0]), "r"(a[1]), "r"(a[2]), "r"(a[3]), "r"(b[0]), "r"(b[1]));
}
__device__ __forceinline__ void ldsm4(uint32_t* r, uint32_t addr) {
    asm volatile("ldmatrix.sync.aligned.m8n8.x4.shared.b16 {%0,%1,%2,%3}, [%4];"
        : "=r"(r[0]), "=r"(r[1]), "=r"(r[2]), "=r"(r[3]) : "r"(addr));
}
__device__ __forceinline__ void ldsm4t(uint32_t* r, uint32_t addr) {
    asm volatile("ldmatrix.sync.aligned.m8n8.x4.trans.shared.b16 {%0,%1,%2,%3}, [%4];"
        : "=r"(r[0]), "=r"(r[1]), "=r"(r[2]), "=r"(r[3]) : "r"(addr));
}
__device__ __forceinline__ uint32_t h2u(float x, float y) {
    __half2 h = __floats2half2_rn(x, y);
    return *(uint32_t*)&h;
}

// ---------------------------------------------------------------------------
// Fused prep: [0,4096) convert q/k/v to fp16; [4096,4352) RoPE tables;
// [4352,8448) transpose+convert the 4 weight matrices.
// ---------------------------------------------------------------------------
__global__ void prep_kernel(const float* __restrict__ q, const float* __restrict__ k,
                            const float* __restrict__ v,
                            const float* __restrict__ W0, const float* __restrict__ W1,
                            const float* __restrict__ W2, const float* __restrict__ W3)
{
    const int bx = blockIdx.x;
    if (bx < 4096) {
        int i = bx * blockDim.x + threadIdx.x;   // 1M float4 per array
        float4 a = ((const float4*)q)[i];
        float4 b = ((const float4*)k)[i];
        float4 c = ((const float4*)v)[i];
        ((__half2*)g_qh)[i*2]   = __floats2half2_rn(a.x, a.y);
        ((__half2*)g_qh)[i*2+1] = __floats2half2_rn(a.z, a.w);
        ((__half2*)g_kh)[i*2]   = __floats2half2_rn(b.x, b.y);
        ((__half2*)g_kh)[i*2+1] = __floats2half2_rn(b.z, b.w);
        ((__half2*)g_vh)[i*2]   = __floats2half2_rn(c.x, c.y);
        ((__half2*)g_vh)[i*2+1] = __floats2half2_rn(c.z, c.w);
    } else if (bx < 4352) {
        int idx = (bx - 4096) * blockDim.x + threadIdx.x;   // 65536
        int i = idx & 31;
        int s = idx >> 5;
        float inv = (float)exp(-((double)i / 32.0) * log(10000.0));
        float ang = (float)s * inv;
        g_cos[idx] = cosf(ang);
        g_sin[idx] = sinf(ang);
    } else {
        __shared__ float t[32][33];
        const int tb  = bx - 4352;
        const int z   = tb >> 10;           // matrix 0..3
        const int rem = tb & 1023;
        const int gx  = rem & 31;
        const int gy  = rem >> 5;
        const float* W = (z == 0) ? W0 : (z == 1) ? W1 : (z == 2) ? W2 : W3;
        __half* Wt = g_Wh + (size_t)z * D_ * D_;
        const int tx = threadIdx.x & 31;
        const int ty = threadIdx.x >> 5;    // 0..7
        int x = gx * 32 + tx;
        int y = gy * 32 + ty;
        #pragma unroll
        for (int j = 0; j < 32; j += 8)
            t[ty + j][tx] = W[(size_t)(y + j) * D_ + x];
        __syncthreads();
        int x2 = gy * 32 + tx;
        int y2 = gx * 32 + ty;
        #pragma unroll
        for (int j = 0; j < 32; j += 8)
            Wt[(size_t)(y2 + j) * D_ + x2] = __float2half_rn(t[tx][ty + j]);
    }
}

// ---------------------------------------------------------------------------
// fp16 GEMM (measured best wmma config): 128x128 tile, BK=64,
// 3-stage cp.async pipeline, one sync/stage, 2 CTA/SM.
// ---------------------------------------------------------------------------
#define GLD 72                   // stage row stride (halves)
#define GBUF 9216                // one matrix buffer (halves)
#define GSTAGE_H 18432           // one stage (A+B) in halves
#define GSTAGE_B 36864           // one stage in bytes

__device__ __forceinline__ void gemm_body(
    const __half* __restrict__ A, const __half* __restrict__ Bt,
    const float* __restrict__ bias, float* __restrict__ Cf, __half* __restrict__ Ch,
    int rope, float oscale)
{
    extern __shared__ __align__(128) char smc[];
    __half* smh = (__half*)smc;
    float (*Cs)[132] = (float(*)[132])smc;

    const int tid = threadIdx.x;
    const int wid = tid >> 5;
    const int wr  = wid >> 2;    // 0..1 -> rows wr*64
    const int wc  = wid & 3;     // 0..3 -> cols wc*32
    const int bm  = blockIdx.y * 128;
    const int bn  = blockIdx.x * 128;

    const uint32_t sb = smem_u32(smc);

    const int r0 = tid >> 3;     // rows r0 + 32j
    const int c8 = tid & 7;
    const __half* Ag = A  + (size_t)(bm + r0) * D_ + c8 * 8;
    const __half* Bg = Bt + (size_t)(bn + r0) * D_ + c8 * 8;
    uint32_t dstA[4], dstB[4];
    #pragma unroll
    for (int j = 0; j < 4; j++) {
        dstA[j] = sb + (uint32_t)((r0 + 32 * j) * GLD + c8 * 8) * 2;
        dstB[j] = dstA[j] + GBUF * 2;
    }

    wmma::fragment<wmma::accumulator, 16, 16, 16, float> acc[4][2];
    #pragma unroll
    for (int s = 0; s < 4; s++)
        #pragma unroll
        for (int f = 0; f < 2; f++) wmma::fill_fragment(acc[s][f], 0.0f);

    #pragma unroll
    for (int j = 0; j < 4; j++) {
        cpa16(dstA[j], Ag + (size_t)j * 32 * D_);
        cpa16(dstB[j], Bg + (size_t)j * 32 * D_);
    }
    CPA_COMMIT();
    #pragma unroll
    for (int j = 0; j < 4; j++) {
        cpa16(dstA[j] + GSTAGE_B, Ag + (size_t)j * 32 * D_ + 64);
        cpa16(dstB[j] + GSTAGE_B, Bg + (size_t)j * 32 * D_ + 64);
    }
    CPA_COMMIT();

    for (int s = 0; s < 16; s++) {
        if (s < 15) CPA_WAIT1(); else CPA_WAIT0();
        __syncthreads();

        if (s + 2 < 16) {
            const uint32_t off = (uint32_t)((s + 2) % 3) * GSTAGE_B;
            #pragma unroll
            for (int j = 0; j < 4; j++) {
                cpa16(dstA[j] + off, Ag + (size_t)j * 32 * D_ + (s + 2) * 64);
                cpa16(dstB[j] + off, Bg + (size_t)j * 32 * D_ + (s + 2) * 64);
            }
            CPA_COMMIT();
        }

        const __half* As = smh + (s % 3) * GSTAGE_H;
        const __half* Bs = As + GBUF;
        #pragma unroll
        for (int ks = 0; ks < 4; ks++) {
            wmma::fragment<wmma::matrix_a, 16, 16, 16, __half, wmma::row_major> a[4];
            wmma::fragment<wmma::matrix_b, 16, 16, 16, __half, wmma::col_major> bf[2];
            #pragma unroll
            for (int t = 0; t < 4; t++)
                wmma::load_matrix_sync(a[t], &As[(wr * 64 + t * 16) * GLD + ks * 16], GLD);
            #pragma unroll
            for (int f = 0; f < 2; f++)
                wmma::load_matrix_sync(bf[f], &Bs[(wc * 32 + f * 16) * GLD + ks * 16], GLD);
            #pragma unroll
            for (int t = 0; t < 4; t++)
                #pragma unroll
                for (int f = 0; f < 2; f++)
                    wmma::mma_sync(acc[t][f], a[t], bf[f], acc[t][f]);
        }
    }
    __syncthreads();

    #pragma unroll
    for (int t = 0; t < 4; t++)
        #pragma unroll
        for (int f = 0; f < 2; f++)
            wmma::store_matrix_sync(&Cs[wr * 64 + t * 16][wc * 32 + f * 16], acc[t][f], 132,
                                    wmma::mem_row_major);
    __syncthreads();

    if (rope) {
        for (int i = tid; i < 128 * 16; i += 256) {
            int r  = i >> 4;
            int rest = i & 15;
            int hp = rest >> 3;
            int c  = hp * 64 + (rest & 7) * 4;
            int wcn = (rest & 7) * 4;
            int sg = (bm + r) & (S_ - 1);
            float4 v1 = *(float4*)&Cs[r][c];
            float4 v2 = *(float4*)&Cs[r][c + 32];
            float4 cw = *(const float4*)(g_cos + sg * 32 + wcn);
            float4 sw = *(const float4*)(g_sin + sg * 32 + wcn);
            float4 b1 = *(const float4*)(bias + bn + c);
            float4 b2 = *(const float4*)(bias + bn + c + 32);
            float4 o1, o2;
            o1.x = (v1.x * cw.x - v2.x * sw.x + b1.x) * oscale;
            o2.x = (v2.x * cw.x + v1.x * sw.x + b2.x) * oscale;
            o1.y = (v1.y * cw.y - v2.y * sw.y + b1.y) * oscale;
            o2.y = (v2.y * cw.y + v1.y * sw.y + b2.y) * oscale;
            o1.z = (v1.z * cw.z - v2.z * sw.z + b1.z) * oscale;
            o2.z = (v2.z * cw.z + v1.z * sw.z + b2.z) * oscale;
            o1.w = (v1.w * cw.w - v2.w * sw.w + b1.w) * oscale;
            o2.w = (v2.w * cw.w + v1.w * sw.w + b2.w) * oscale;
            __half* p1 = Ch + (size_t)(bm + r) * D_ + bn + c;
            __half* p2 = p1 + 32;
            *(__half2*)(p1)     = __floats2half2_rn(o1.x, o1.y);
            *(__half2*)(p1 + 2) = __floats2half2_rn(o1.z, o1.w);
            *(__half2*)(p2)     = __floats2half2_rn(o2.x, o2.y);
            *(__half2*)(p2 + 2) = __floats2half2_rn(o2.z, o2.w);
        }
    } else {
        for (int i = tid; i < 128 * 32; i += 256) {
            int r = i >> 5;
            int c = (i & 31) * 4;
            float4 v  = *(float4*)&Cs[r][c];
            float4 bb = *(const float4*)(bias + bn + c);
            v.x += bb.x; v.y += bb.y; v.z += bb.z; v.w += bb.w;
            __half* p = Ch + (size_t)(bm + r) * D_ + bn + c;
            *(__half2*)(p)     = __floats2half2_rn(v.x, v.y);
            *(__half2*)(p + 2) = __floats2half2_rn(v.z, v.w);
        }
    }
}

__global__ __launch_bounds__(256, 2) void qkv_kernel(
    const float* __restrict__ bq, const float* __restrict__ bk, const float* __restrict__ bv)
{
    if (blockIdx.z == 0)      gemm_body(g_qh, g_Wh,               bq, nullptr, g_Qh, 1, 0.125f * LOG2E);
    else if (blockIdx.z == 1) gemm_body(g_kh, g_Wh + 1 * D_ * D_, bk, nullptr, g_Kh, 1, 1.0f);
    else                      gemm_body(g_vh, g_Wh + 2 * D_ * D_, bv, nullptr, g_Vh, 0, 1.0f);
}

// ---------------------------------------------------------------------------
// oproj GEMM, 128x64 tiles (512 CTAs -> 1.73 waves): BK=64, 3-stage cp.async,
// 8 warps 4x2, warp tile 32x32 (acc 2x2), fp32 epilogue. 2 CTA/SM.
// smem: 3 x (A 128x72 + B 64x72) halves = 82944 B.
// ---------------------------------------------------------------------------
#define NLD 72
#define N_ABUF 9216              // A buffer halves
#define N_BBUF 4608              // B buffer halves
#define N_STAGE_H 13824
#define N_STAGE_B 27648

__global__ __launch_bounds__(256, 2) void oproj_kernel(
    const float* __restrict__ bias, float* __restrict__ out)
{
    extern __shared__ __align__(128) char smc[];
    __half* smh = (__half*)smc;
    float (*Cs)[68] = (float(*)[68])smc;    // 128*68*4 = 34816 B <= stage arena

    const __half* A  = g_Ath;
    const __half* Bt = g_Wh + 3 * (size_t)D_ * D_;

    const int tid = threadIdx.x;
    const int wid = tid >> 5;
    const int wr  = wid >> 1;    // 0..3 -> rows wr*32
    const int wc  = wid & 1;     // 0..1 -> cols wc*32
    const int bm  = blockIdx.y * 128;
    const int bn  = blockIdx.x * 64;

    const uint32_t sb = smem_u32(smc);

    // A: 4 chunks/thread (rows r0+32j); B: 2 chunks/thread (rows r0, r0+32)
    const int r0 = tid >> 3;     // 0..31
    const int c8 = tid & 7;
    const __half* Ag = A  + (size_t)(bm + r0) * D_ + c8 * 8;
    const __half* Bg = Bt + (size_t)(bn + r0) * D_ + c8 * 8;
    uint32_t dstA[4], dstB[2];
    #pragma unroll
    for (int j = 0; j < 4; j++)
        dstA[j] = sb + (uint32_t)((r0 + 32 * j) * NLD + c8 * 8) * 2;
    #pragma unroll
    for (int j = 0; j < 2; j++)
        dstB[j] = sb + (uint32_t)(N_ABUF + (r0 + 32 * j) * NLD + c8 * 8) * 2;

    wmma::fragment<wmma::accumulator, 16, 16, 16, float> acc[2][2];
    #pragma unroll
    for (int t = 0; t < 2; t++)
        #pragma unroll
        for (int f = 0; f < 2; f++) wmma::fill_fragment(acc[t][f], 0.0f);

    // Prologue: stages 0, 1
    #pragma unroll
    for (int j = 0; j < 4; j++) cpa16(dstA[j], Ag + (size_t)j * 32 * D_);
    #pragma unroll
    for (int j = 0; j < 2; j++) cpa16(dstB[j], Bg + (size_t)j * 32 * D_);
    CPA_COMMIT();
    #pragma unroll
    for (int j = 0; j < 4; j++) cpa16(dstA[j] + N_STAGE_B, Ag + (size_t)j * 32 * D_ + 64);
    #pragma unroll
    for (int j = 0; j < 2; j++) cpa16(dstB[j] + N_STAGE_B, Bg + (size_t)j * 32 * D_ + 64);
    CPA_COMMIT();

    for (int s = 0; s < 16; s++) {
        if (s < 15) CPA_WAIT1(); else CPA_WAIT0();
        __syncthreads();

        if (s + 2 < 16) {
            const uint32_t off = (uint32_t)((s + 2) % 3) * N_STAGE_B;
            #pragma unroll
            for (int j = 0; j < 4; j++) cpa16(dstA[j] + off, Ag + (size_t)j * 32 * D_ + (s + 2) * 64);
            #pragma unroll
            for (int j = 0; j < 2; j++) cpa16(dstB[j] + off, Bg + (size_t)j * 32 * D_ + (s + 2) * 64);
            CPA_COMMIT();
        }

        const __half* As = smh + (s % 3) * N_STAGE_H;
        const __half* Bs = As + N_ABUF;
        #pragma unroll
        for (int ks = 0; ks < 4; ks++) {
            wmma::fragment<wmma::matrix_a, 16, 16, 16, __half, wmma::row_major> a[2];
            wmma::fragment<wmma::matrix_b, 16, 16, 16, __half, wmma::col_major> bf[2];
            #pragma unroll
            for (int t = 0; t < 2; t++)
                wmma::load_matrix_sync(a[t], &As[(wr * 32 + t * 16) * NLD + ks * 16], NLD);
            #pragma unroll
            for (int f = 0; f < 2; f++)
                wmma::load_matrix_sync(bf[f], &Bs[(wc * 32 + f * 16) * NLD + ks * 16], NLD);
            #pragma unroll
            for (int t = 0; t < 2; t++)
                #pragma unroll
                for (int f = 0; f < 2; f++)
                    wmma::mma_sync(acc[t][f], a[t], bf[f], acc[t][f]);
        }
    }
    __syncthreads();

    #pragma unroll
    for (int t = 0; t < 2; t++)
        #pragma unroll
        for (int f = 0; f < 2; f++)
            wmma::store_matrix_sync(&Cs[wr * 32 + t * 16][wc * 32 + f * 16], acc[t][f], 68,
                                    wmma::mem_row_major);
    __syncthreads();

    for (int i = tid; i < 128 * 16; i += 256) {
        int r = i >> 4;
        int c = (i & 15) * 4;
        float4 v  = *(float4*)&Cs[r][c];
        float4 bb = *(const float4*)(bias + bn + c);
        v.x += bb.x; v.y += bb.y; v.z += bb.z; v.w += bb.w;
        *(float4*)(out + (size_t)(bm + r) * D_ + bn + c) = v;
    }
}

// ---------------------------------------------------------------------------
// Flash attention FA2 (registers), base-2 softmax, LPT grid, warp block-skip,
// rescale-skip. (unchanged from R13)
// ---------------------------------------------------------------------------
#define FW_Q 0               // 128 x 72 halves = 18432 B
#define FW_K 18432           // 2 x (64 x 72) halves
#define FW_V 36864
#define FW_TOT 55296
#define KVS 9216             // one K/V buffer bytes

__global__ __launch_bounds__(256, 2) void flash_kernel()
{
    extern __shared__ __align__(128) char smc[];
    const int idx = blockIdx.x;
    const int qb = 15 - (idx >> 5);
    const int h  = idx & 15;
    const int b  = (idx >> 4) & 1;

    const int tid  = threadIdx.x;
    const int w    = tid >> 5;
    const int lane = tid & 31;
    const int q0   = qb * 128;
    const int w16  = w * 16;

    const uint32_t sb = smem_u32(smc);
    const __half* Qg = g_Qh + ((size_t)b * S_ + q0) * D_ + h * DK_;
    const __half* Kb = g_Kh + ((size_t)b * S_) * D_ + h * DK_;
    const __half* Vb = g_Vh + ((size_t)b * S_) * D_ + h * DK_;

    #pragma unroll
    for (int j = 0; j < 4; j++) {
        int i = tid + j * 256;
        int r = i >> 3, c8 = i & 7;
        cpa16(sb + FW_Q + (uint32_t)(r * 72 + c8 * 8) * 2, Qg + (size_t)r * D_ + c8 * 8);
    }
    #pragma unroll
    for (int j = 0; j < 2; j++) {
        int i = tid + j * 256;
        int r = i >> 3, c8 = i & 7;
        cpa16(sb + FW_K + (uint32_t)(r * 72 + c8 * 8) * 2, Kb + (size_t)r * D_ + c8 * 8);
        cpa16(sb + FW_V + (uint32_t)(r * 72 + c8 * 8) * 2, Vb + (size_t)r * D_ + c8 * 8);
    }
    CPA_COMMIT();
    CPA_WAIT0();
    __syncthreads();

    uint32_t aq[4][4];
    {
        uint32_t qa = sb + FW_Q +
            (uint32_t)((w16 + (lane & 15)) * 72 + ((lane & 16) ? 8 : 0)) * 2;
        #pragma unroll
        for (int kf = 0; kf < 4; kf++) ldsm4(aq[kf], qa + kf * 32);
    }

    float o[8][4];
    #pragma unroll
    for (int nf = 0; nf < 8; nf++) { o[nf][0]=0.f; o[nf][1]=0.f; o[nf][2]=0.f; o[nf][3]=0.f; }
    float m0 = -1e30f, m1 = -1e30f, l0 = 0.f, l1 = 0.f;

    const int nkb = 2 * qb + 2;
    const int rq0 = q0 + w16 + (lane >> 2);
    const int cc0 = (lane & 3) * 2;
    const uint32_t lmo = (uint32_t)((lane & 15) * 72 + ((lane & 16) ? 8 : 0)) * 2;

    for (int kb = 0; kb < nkb; kb++) {
        const int cur = kb & 1, nxt = cur ^ 1;

        if (kb + 1 < nkb) {
            const __half* Kg = Kb + (size_t)(kb + 1) * 64 * D_;
            const __half* Vg = Vb + (size_t)(kb + 1) * 64 * D_;
            #pragma unroll
            for (int j = 0; j < 2; j++) {
                int i = tid + j * 256;
                int r = i >> 3, c8 = i & 7;
                uint32_t off = (uint32_t)(nxt * KVS + (r * 72 + c8 * 8) * 2);
                cpa16(sb + FW_K + off, Kg + (size_t)r * D_ + c8 * 8);
                cpa16(sb + FW_V + off, Vg + (size_t)r * D_ + c8 * 8);
            }
            CPA_COMMIT();
        }

        const bool active = (kb * 64 <= q0 + w16 + 15);
        if (active) {
            float s[8][4];
            #pragma unroll
            for (int nf = 0; nf < 8; nf++) { s[nf][0]=0.f; s[nf][1]=0.f; s[nf][2]=0.f; s[nf][3]=0.f; }
            {
                uint32_t ka = sb + FW_K + cur * KVS + lmo;
                #pragma unroll
                for (int kf = 0; kf < 4; kf++) {
                    #pragma unroll
                    for (int np = 0; np < 4; np++) {
                        uint32_t bk[4];
                        ldsm4(bk, ka + (uint32_t)(np * 16 * 72) * 2 + kf * 32);
                        uint32_t b0[2] = { bk[0], bk[2] };
                        uint32_t b1[2] = { bk[1], bk[3] };
                        mma16816(s[2*np],   aq[kf], b0);
                        mma16816(s[2*np+1], aq[kf], b1);
                    }
                }
            }

            if (kb >= 2 * qb) {
                #pragma unroll
                for (int nf = 0; nf < 8; nf++) {
                    int c = kb * 64 + nf * 8 + cc0;
                    if (c     > rq0)     s[nf][0] = -1e30f;
                    if (c + 1 > rq0)     s[nf][1] = -1e30f;
                    if (c     > rq0 + 8) s[nf][2] = -1e30f;
                    if (c + 1 > rq0 + 8) s[nf][3] = -1e30f;
                }
            }

            float mx0 = -1e30f, mx1 = -1e30f;
            #pragma unroll
            for (int nf = 0; nf < 8; nf++) {
                mx0 = fmaxf(mx0, fmaxf(s[nf][0], s[nf][1]));
                mx1 = fmaxf(mx1, fmaxf(s[nf][2], s[nf][3]));
            }
            mx0 = fmaxf(mx0, __shfl_xor_sync(0xffffffffu, mx0, 1));
            mx0 = fmaxf(mx0, __shfl_xor_sync(0xffffffffu, mx0, 2));
            mx1 = fmaxf(mx1, __shfl_xor_sync(0xffffffffu, mx1, 1));
            mx1 = fmaxf(mx1, __shfl_xor_sync(0xffffffffu, mx1, 2));
            float mn0 = fmaxf(m0, mx0), mn1 = fmaxf(m1, mx1);

            uint32_t pa[4][4];
            float sum0 = 0.f, sum1 = 0.f;
            #pragma unroll
            for (int np = 0; np < 4; np++) {
                float p00 = exp2f(s[2*np][0]   - mn0), p01 = exp2f(s[2*np][1]   - mn0);
                float p02 = exp2f(s[2*np][2]   - mn1), p03 = exp2f(s[2*np][3]   - mn1);
                float p10 = exp2f(s[2*np+1][0] - mn0), p11 = exp2f(s[2*np+1][1] - mn0);
                float p12 = exp2f(s[2*np+1][2] - mn1), p13 = exp2f(s[2*np+1][3] - mn1);
                sum0 += p00 + p01 + p10 + p11;
                sum1 += p02 + p03 + p12 + p13;
                pa[np][0] = h2u(p00, p01);
                pa[np][1] = h2u(p02, p03);
                pa[np][2] = h2u(p10, p11);
                pa[np][3] = h2u(p12, p13);
            }
            sum0 += __shfl_xor_sync(0xffffffffu, sum0, 1);
            sum0 += __shfl_xor_sync(0xffffffffu, sum0, 2);
            sum1 += __shfl_xor_sync(0xffffffffu, sum1, 1);
            sum1 += __shfl_xor_sync(0xffffffffu, sum1, 2);

            const bool moved = (mn0 > m0) | (mn1 > m1);
            if (__any_sync(0xffffffffu, moved)) {
                float c0 = exp2f(m0 - mn0), c1 = exp2f(m1 - mn1);
                l0 = l0 * c0 + sum0;
                l1 = l1 * c1 + sum1;
                #pragma unroll
                for (int nf = 0; nf < 8; nf++) {
                    o[nf][0] *= c0; o[nf][1] *= c0; o[nf][2] *= c1; o[nf][3] *= c1;
                }
            } else {
                l0 += sum0;
                l1 += sum1;
            }
            m0 = mn0; m1 = mn1;

            {
                uint32_t va = sb + FW_V + cur * KVS + lmo;
                #pragma unroll
                for (int kf = 0; kf < 4; kf++) {
                    #pragma unroll
                    for (int np = 0; np < 4; np++) {
                        uint32_t bv[4];
                        ldsm4t(bv, va + (uint32_t)(kf * 16 * 72) * 2 + np * 32);
                        uint32_t b0[2] = { bv[0], bv[1] };
                        uint32_t b1[2] = { bv[2], bv[3] };
                        mma16816(o[2*np],   pa[kf], b0);
                        mma16816(o[2*np+1], pa[kf], b1);
                    }
                }
            }
        }

        if (kb + 1 < nkb) CPA_WAIT0();
        __syncthreads();
    }

    {
        float il0 = 1.f / l0, il1 = 1.f / l1;
        __half* Og  = g_Ath + ((size_t)b * S_ + rq0) * D_ + h * DK_ + cc0;
        __half* Og8 = Og + 8 * D_;
        #pragma unroll
        for (int nf = 0; nf < 8; nf++) {
            *(__half2*)(Og  + nf * 8) = __floats2half2_rn(o[nf][0] * il0, o[nf][1] * il0);
            *(__half2*)(Og8 + nf * 8) = __floats2half2_rn(o[nf][2] * il1, o[nf][3] * il1);
        }
    }
}

// ---------------------------------------------------------------------------
// Host launcher
// ---------------------------------------------------------------------------
extern "C" void kernel_launch(void* const* d_in, const int* in_sizes, int n_in,
                              void* d_out, int out_size)
{
    const float* q  = (const float*)d_in[0];
    const float* k  = (const float*)d_in[1];
    const float* v  = (const float*)d_in[2];
    const float* Wq = (const float*)d_in[4];
    const float* bq = (const float*)d_in[5];
    const float* Wk = (const float*)d_in[6];
    const float* bk = (const float*)d_in[7];
    const float* Wv = (const float*)d_in[8];
    const float* bv = (const float*)d_in[9];
    const float* Wo = (const float*)d_in[10];
    const float* bo = (const float*)d_in[11];
    float* out = (float*)d_out;

    prep_kernel<<<4096 + 256 + 4096, 256>>>(q, k, v, Wq, Wk, Wv, Wo);

    size_t gsmem = 3 * GSTAGE_B;                // 110592 B
    cudaFuncSetAttribute(qkv_kernel, cudaFuncAttributeMaxDynamicSharedMemorySize, (int)gsmem);
    qkv_kernel<<<dim3(8, 32, 3), 256, gsmem>>>(bq, bk, bv);

    size_t fsmem = FW_TOT;                      // 55296 B
    cudaFuncSetAttribute(flash_kernel, cudaFuncAttributeMaxDynamicSharedMemorySize, (int)fsmem);
    flash_kernel<<<512, 256, fsmem>>>();

    size_t osmem = 3 * N_STAGE_B;               // 82944 B
    cudaFuncSetAttribute(oproj_kernel, cudaFuncAttributeMaxDynamicSharedMemorySize, (int)osmem);
    oproj_kernel<<<dim3(16, 32), 256, osmem>>>(bo, out);
}

// round 16
// speedup vs baseline: 1.0333x; 1.0333x over previous
#include <cuda_runtime.h>
#include <mma.h>
#include <cuda_fp16.h>
#include <math.h>
#include <stdint.h>

using namespace nvcuda;

#define B_   2
#define S_   2048
#define D_   1024
#define H_   16
#define DK_  64
#define MTOT (B_ * S_)   // 4096
#define LOG2E 1.44269504088896340736f

__device__ __half g_qh[MTOT * D_];
__device__ __half g_kh[MTOT * D_];
__device__ __half g_vh[MTOT * D_];
__device__ __half g_Wh[4 * D_ * D_];    // transposed weights [N,K], fp16
__device__ __half g_Qh[MTOT * D_];      // projected Q (rope, x 0.125*log2e)
__device__ __half g_Kh[MTOT * D_];      // projected K (rope)
__device__ __half g_Vh[MTOT * D_];      // projected V
__device__ __half g_Ath[MTOT * D_];     // attention output
__device__ float  g_cos[S_ * 32];
__device__ float  g_sin[S_ * 32];

__device__ __forceinline__ uint32_t smem_u32(const void* p) {
    uint32_t a;
    asm("{ .reg .u64 t; cvta.to.shared.u64 t, %1; cvt.u32.u64 %0, t; }" : "=r"(a) : "l"(p));
    return a;
}
__device__ __forceinline__ void cpa16(uint32_t dst, const void* src) {
    asm volatile("cp.async.cg.shared.global [%0], [%1], 16;" :: "r"(dst), "l"(src) : "memory");
}
#define CPA_COMMIT() asm volatile("cp.async.commit_group;" ::: "memory")
#define CPA_WAIT1()  asm volatile("cp.async.wait_group 1;" ::: "memory")
#define CPA_WAIT0()  asm volatile("cp.async.wait_group 0;" ::: "memory")

__device__ __forceinline__ void mma16816(float* c, const uint32_t* a, const uint32_t* b) {
    asm volatile("mma.sync.aligned.m16n8k16.row.col.f32.f16.f16.f32 "
        "{%0,%1,%2,%3}, {%4,%5,%6,%7}, {%8,%9}, {%0,%1,%2,%3};"
        : "+f"(c[0]), "+f"(c[1]), "+f"(c[2]), "+f"(c[3])
        : "r"(a[0]), "r"(a[1]), "r"(a[2]), "r"(a[3]), "r"(b[0]), "r"(b[1]));
}
__device__ __forceinline__ void ldsm4(uint32_t* r, uint32_t addr) {
    asm volatile("ldmatrix.sync.aligned.m8n8.x4.shared.b16 {%0,%1,%2,%3}, [%4];"
        : "=r"(r[0]), "=r"(r[1]), "=r"(r[2]), "=r"(r[3]) : "r"(addr));
}
__device__ __forceinline__ void ldsm4t(uint32_t* r, uint32_t addr) {
    asm volatile("ldmatrix.sync.aligned.m8n8.x4.trans.shared.b16 {%0,%1,%2,%3}, [%4];"
        : "=r"(r[0]), "=r"(r[1]), "=r"(r[2]), "=r"(r[3]) : "r"(addr));
}
__device__ __forceinline__ uint32_t h2u(float x, float y) {
    __half2 h = __floats2half2_rn(x, y);
    return *(uint32_t*)&h;
}

// ---------------------------------------------------------------------------
// Fused prep: [0,4096) convert q/k/v; [4096,4352) RoPE tables;
// [4352,8448) transpose+convert the 4 weight matrices.
// ---------------------------------------------------------------------------
__global__ void prep_kernel(const float* __restrict__ q, const float* __restrict__ k,
                            const float* __restrict__ v,
                            const float* __restrict__ W0, const float* __restrict__ W1,
                            const float* __restrict__ W2, const float* __restrict__ W3)
{
    const int bx = blockIdx.x;
    if (bx < 4096) {
        int i = bx * blockDim.x + threadIdx.x;
        float4 a = ((const float4*)q)[i];
        float4 b = ((const float4*)k)[i];
        float4 c = ((const float4*)v)[i];
        ((__half2*)g_qh)[i*2]   = __floats2half2_rn(a.x, a.y);
        ((__half2*)g_qh)[i*2+1] = __floats2half2_rn(a.z, a.w);
        ((__half2*)g_kh)[i*2]   = __floats2half2_rn(b.x, b.y);
        ((__half2*)g_kh)[i*2+1] = __floats2half2_rn(b.z, b.w);
        ((__half2*)g_vh)[i*2]   = __floats2half2_rn(c.x, c.y);
        ((__half2*)g_vh)[i*2+1] = __floats2half2_rn(c.z, c.w);
    } else if (bx < 4352) {
        int idx = (bx - 4096) * blockDim.x + threadIdx.x;
        int i = idx & 31;
        int s = idx >> 5;
        float inv = (float)exp(-((double)i / 32.0) * log(10000.0));
        float ang = (float)s * inv;
        g_cos[idx] = cosf(ang);
        g_sin[idx] = sinf(ang);
    } else {
        __shared__ float t[32][33];
        const int tb  = bx - 4352;
        const int z   = tb >> 10;
        const int rem = tb & 1023;
        const int gx  = rem & 31;
        const int gy  = rem >> 5;
        const float* W = (z == 0) ? W0 : (z == 1) ? W1 : (z == 2) ? W2 : W3;
        __half* Wt = g_Wh + (size_t)z * D_ * D_;
        const int tx = threadIdx.x & 31;
        const int ty = threadIdx.x >> 5;
        int x = gx * 32 + tx;
        int y = gy * 32 + ty;
        #pragma unroll
        for (int j = 0; j < 32; j += 8)
            t[ty + j][tx] = W[(size_t)(y + j) * D_ + x];
        __syncthreads();
        int x2 = gy * 32 + tx;
        int y2 = gx * 32 + ty;
        #pragma unroll
        for (int j = 0; j < 32; j += 8)
            Wt[(size_t)(y2 + j) * D_ + x2] = __float2half_rn(t[tx][ty + j]);
    }
}

// ---------------------------------------------------------------------------
// fp16 GEMM (measured best): 128x128 tile, BK=64, 3-stage cp.async, 2 CTA/SM.
// ---------------------------------------------------------------------------
#define GLD 72
#define GBUF 9216
#define GSTAGE_H 18432
#define GSTAGE_B 36864

__device__ __forceinline__ void gemm_body(
    const __half* __restrict__ A, const __half* __restrict__ Bt,
    const float* __restrict__ bias, float* __restrict__ Cf, __half* __restrict__ Ch,
    int rope, float oscale)
{
    extern __shared__ __align__(128) char smc[];
    __half* smh = (__half*)smc;
    float (*Cs)[132] = (float(*)[132])smc;

    const int tid = threadIdx.x;
    const int wid = tid >> 5;
    const int wr  = wid >> 2;
    const int wc  = wid & 3;
    const int bm  = blockIdx.y * 128;
    const int bn  = blockIdx.x * 128;

    const uint32_t sb = smem_u32(smc);

    const int r0 = tid >> 3;
    const int c8 = tid & 7;
    const __half* Ag = A  + (size_t)(bm + r0) * D_ + c8 * 8;
    const __half* Bg = Bt + (size_t)(bn + r0) * D_ + c8 * 8;
    uint32_t dstA[4], dstB[4];
    #pragma unroll
    for (int j = 0; j < 4; j++) {
        dstA[j] = sb + (uint32_t)((r0 + 32 * j) * GLD + c8 * 8) * 2;
        dstB[j] = dstA[j] + GBUF * 2;
    }

    wmma::fragment<wmma::accumulator, 16, 16, 16, float> acc[4][2];
    #pragma unroll
    for (int s = 0; s < 4; s++)
        #pragma unroll
        for (int f = 0; f < 2; f++) wmma::fill_fragment(acc[s][f], 0.0f);

    #pragma unroll
    for (int j = 0; j < 4; j++) {
        cpa16(dstA[j], Ag + (size_t)j * 32 * D_);
        cpa16(dstB[j], Bg + (size_t)j * 32 * D_);
    }
    CPA_COMMIT();
    #pragma unroll
    for (int j = 0; j < 4; j++) {
        cpa16(dstA[j] + GSTAGE_B, Ag + (size_t)j * 32 * D_ + 64);
        cpa16(dstB[j] + GSTAGE_B, Bg + (size_t)j * 32 * D_ + 64);
    }
    CPA_COMMIT();

    for (int s = 0; s < 16; s++) {
        if (s < 15) CPA_WAIT1(); else CPA_WAIT0();
        __syncthreads();

        if (s + 2 < 16) {
            const uint32_t off = (uint32_t)((s + 2) % 3) * GSTAGE_B;
            #pragma unroll
            for (int j = 0; j < 4; j++) {
                cpa16(dstA[j] + off, Ag + (size_t)j * 32 * D_ + (s + 2) * 64);
                cpa16(dstB[j] + off, Bg + (size_t)j * 32 * D_ + (s + 2) * 64);
            }
            CPA_COMMIT();
        }

        const __half* As = smh + (s % 3) * GSTAGE_H;
        const __half* Bs = As + GBUF;
        #pragma unroll
        for (int ks = 0; ks < 4; ks++) {
            wmma::fragment<wmma::matrix_a, 16, 16, 16, __half, wmma::row_major> a[4];
            wmma::fragment<wmma::matrix_b, 16, 16, 16, __half, wmma::col_major> bf[2];
            #pragma unroll
            for (int t = 0; t < 4; t++)
                wmma::load_matrix_sync(a[t], &As[(wr * 64 + t * 16) * GLD + ks * 16], GLD);
            #pragma unroll
            for (int f = 0; f < 2; f++)
                wmma::load_matrix_sync(bf[f], &Bs[(wc * 32 + f * 16) * GLD + ks * 16], GLD);
            #pragma unroll
            for (int t = 0; t < 4; t++)
                #pragma unroll
                for (int f = 0; f < 2; f++)
                    wmma::mma_sync(acc[t][f], a[t], bf[f], acc[t][f]);
        }
    }
    __syncthreads();

    #pragma unroll
    for (int t = 0; t < 4; t++)
        #pragma unroll
        for (int f = 0; f < 2; f++)
            wmma::store_matrix_sync(&Cs[wr * 64 + t * 16][wc * 32 + f * 16], acc[t][f], 132,
                                    wmma::mem_row_major);
    __syncthreads();

    if (rope) {
        for (int i = tid; i < 128 * 16; i += 256) {
            int r  = i >> 4;
            int rest = i & 15;
            int hp = rest >> 3;
            int c  = hp * 64 + (rest & 7) * 4;
            int wcn = (rest & 7) * 4;
            int sg = (bm + r) & (S_ - 1);
            float4 v1 = *(float4*)&Cs[r][c];
            float4 v2 = *(float4*)&Cs[r][c + 32];
            float4 cw = *(const float4*)(g_cos + sg * 32 + wcn);
            float4 sw = *(const float4*)(g_sin + sg * 32 + wcn);
            float4 b1 = *(const float4*)(bias + bn + c);
            float4 b2 = *(const float4*)(bias + bn + c + 32);
            float4 o1, o2;
            o1.x = (v1.x * cw.x - v2.x * sw.x + b1.x) * oscale;
            o2.x = (v2.x * cw.x + v1.x * sw.x + b2.x) * oscale;
            o1.y = (v1.y * cw.y - v2.y * sw.y + b1.y) * oscale;
            o2.y = (v2.y * cw.y + v1.y * sw.y + b2.y) * oscale;
            o1.z = (v1.z * cw.z - v2.z * sw.z + b1.z) * oscale;
            o2.z = (v2.z * cw.z + v1.z * sw.z + b2.z) * oscale;
            o1.w = (v1.w * cw.w - v2.w * sw.w + b1.w) * oscale;
            o2.w = (v2.w * cw.w + v1.w * sw.w + b2.w) * oscale;
            __half* p1 = Ch + (size_t)(bm + r) * D_ + bn + c;
            __half* p2 = p1 + 32;
            *(__half2*)(p1)     = __floats2half2_rn(o1.x, o1.y);
            *(__half2*)(p1 + 2) = __floats2half2_rn(o1.z, o1.w);
            *(__half2*)(p2)     = __floats2half2_rn(o2.x, o2.y);
            *(__half2*)(p2 + 2) = __floats2half2_rn(o2.z, o2.w);
        }
    } else if (Ch) {
        for (int i = tid; i < 128 * 32; i += 256) {
            int r = i >> 5;
            int c = (i & 31) * 4;
            float4 v  = *(float4*)&Cs[r][c];
            float4 bb = *(const float4*)(bias + bn + c);
            v.x += bb.x; v.y += bb.y; v.z += bb.z; v.w += bb.w;
            __half* p = Ch + (size_t)(bm + r) * D_ + bn + c;
            *(__half2*)(p)     = __floats2half2_rn(v.x, v.y);
            *(__half2*)(p + 2) = __floats2half2_rn(v.z, v.w);
        }
    } else {
        for (int i = tid; i < 128 * 32; i += 256) {
            int r = i >> 5;
            int c = (i & 31) * 4;
            float4 v  = *(float4*)&Cs[r][c];
            float4 bb = *(const float4*)(bias + bn + c);
            v.x += bb.x; v.y += bb.y; v.z += bb.z; v.w += bb.w;
            *(float4*)(Cf + (size_t)(bm + r) * D_ + bn + c) = v;
        }
    }
}

__global__ __launch_bounds__(256, 2) void qkv_kernel(
    const float* __restrict__ bq, const float* __restrict__ bk, const float* __restrict__ bv)
{
    if (blockIdx.z == 0)      gemm_body(g_qh, g_Wh,               bq, nullptr, g_Qh, 1, 0.125f * LOG2E);
    else if (blockIdx.z == 1) gemm_body(g_kh, g_Wh + 1 * D_ * D_, bk, nullptr, g_Kh, 1, 1.0f);
    else                      gemm_body(g_vh, g_Wh + 2 * D_ * D_, bv, nullptr, g_Vh, 0, 1.0f);
}

__global__ __launch_bounds__(256, 2) void oproj_kernel(
    const float* __restrict__ bo, float* __restrict__ out)
{
    gemm_body(g_Ath, g_Wh + 3 * D_ * D_, bo, out, nullptr, 0, 1.0f);
}

// ---------------------------------------------------------------------------
// Flash attention FA2 (registers), base-2 softmax, LPT grid, warp block-skip,
// rescale-skip. K/V TRIPLE-buffered; full 2-chunk/thread staging (512 chunks
// per 64x64 tile). Wait at top of iter (wait_group 1), issue kb+2 after.
// ---------------------------------------------------------------------------
#define FW_Q 0               // 128 x 72 halves = 18432 B
#define FW_K 18432           // 3 x (64 x 72) halves = 27648 B
#define FW_V 46080
#define FW_TOT 73728
#define KVS 9216             // one K/V buffer bytes

__global__ __launch_bounds__(256, 2) void flash_kernel()
{
    extern __shared__ __align__(128) char smc[];
    const int idx = blockIdx.x;
    const int qb = 15 - (idx >> 5);
    const int h  = idx & 15;
    const int b  = (idx >> 4) & 1;

    const int tid  = threadIdx.x;
    const int w    = tid >> 5;
    const int lane = tid & 31;
    const int q0   = qb * 128;
    const int w16  = w * 16;

    const uint32_t sb = smem_u32(smc);
    const __half* Qg = g_Qh + ((size_t)b * S_ + q0) * D_ + h * DK_;
    const __half* Kb = g_Kh + ((size_t)b * S_) * D_ + h * DK_;
    const __half* Vb = g_Vh + ((size_t)b * S_) * D_ + h * DK_;

    const int nkb = 2 * qb + 2;   // >= 2 always

    // K/V staging geometry: 2 chunks per thread per tile (512 chunks total)
    const int kvr0 = tid >> 3;          // rows kvr0, kvr0+32
    const int kvc  = tid & 7;
    const uint32_t kvo0 = (uint32_t)(kvr0 * 72 + kvc * 8) * 2;
    const uint32_t kvo1 = (uint32_t)((kvr0 + 32) * 72 + kvc * 8) * 2;

    // Prologue: group0 = Q + K0/V0, group1 = K1/V1
    #pragma unroll
    for (int j = 0; j < 4; j++) {
        int i = tid + j * 256;
        int r = i >> 3, c8 = i & 7;
        cpa16(sb + FW_Q + (uint32_t)(r * 72 + c8 * 8) * 2, Qg + (size_t)r * D_ + c8 * 8);
    }
    cpa16(sb + FW_K + kvo0, Kb + (size_t)kvr0 * D_ + kvc * 8);
    cpa16(sb + FW_K + kvo1, Kb + (size_t)(kvr0 + 32) * D_ + kvc * 8);
    cpa16(sb + FW_V + kvo0, Vb + (size_t)kvr0 * D_ + kvc * 8);
    cpa16(sb + FW_V + kvo1, Vb + (size_t)(kvr0 + 32) * D_ + kvc * 8);
    CPA_COMMIT();
    {
        const __half* Kg = Kb + (size_t)64 * D_;
        const __half* Vg = Vb + (size_t)64 * D_;
        cpa16(sb + FW_K + KVS + kvo0, Kg + (size_t)kvr0 * D_ + kvc * 8);
        cpa16(sb + FW_K + KVS + kvo1, Kg + (size_t)(kvr0 + 32) * D_ + kvc * 8);
        cpa16(sb + FW_V + KVS + kvo0, Vg + (size_t)kvr0 * D_ + kvc * 8);
        cpa16(sb + FW_V + KVS + kvo1, Vg + (size_t)(kvr0 + 32) * D_ + kvc * 8);
        CPA_COMMIT();
    }

    CPA_WAIT1();          // group0 (Q + K0/V0) complete; group1 may be in flight
    __syncthreads();

    uint32_t aq[4][4];
    {
        uint32_t qa = sb + FW_Q +
            (uint32_t)((w16 + (lane & 15)) * 72 + ((lane & 16) ? 8 : 0)) * 2;
        #pragma unroll
        for (int kf = 0; kf < 4; kf++) ldsm4(aq[kf], qa + kf * 32);
    }

    float o[8][4];
    #pragma unroll
    for (int nf = 0; nf < 8; nf++) { o[nf][0]=0.f; o[nf][1]=0.f; o[nf][2]=0.f; o[nf][3]=0.f; }
    float m0 = -1e30f, m1 = -1e30f, l0 = 0.f, l1 = 0.f;

    const int rq0 = q0 + w16 + (lane >> 2);
    const int cc0 = (lane & 3) * 2;
    const uint32_t lmo = (uint32_t)((lane & 15) * 72 + ((lane & 16) ? 8 : 0)) * 2;

    for (int kb = 0; kb < nkb; kb++) {
        const int cur = kb % 3;

        // At top of iter kb, committed groups are 0..kb+1; wait_group 1
        // guarantees group kb is complete.
        if (kb + 1 < nkb) CPA_WAIT1(); else CPA_WAIT0();
        __syncthreads();   // retires last iter's reads of buffer (kb+2)%3

        if (kb + 2 < nkb) {
            const __half* Kg = Kb + (size_t)(kb + 2) * 64 * D_;
            const __half* Vg = Vb + (size_t)(kb + 2) * 64 * D_;
            uint32_t off = (uint32_t)((kb + 2) % 3) * KVS;
            cpa16(sb + FW_K + off + kvo0, Kg + (size_t)kvr0 * D_ + kvc * 8);
            cpa16(sb + FW_K + off + kvo1, Kg + (size_t)(kvr0 + 32) * D_ + kvc * 8);
            cpa16(sb + FW_V + off + kvo0, Vg + (size_t)kvr0 * D_ + kvc * 8);
            cpa16(sb + FW_V + off + kvo1, Vg + (size_t)(kvr0 + 32) * D_ + kvc * 8);
            CPA_COMMIT();
        }

        const bool active = (kb * 64 <= q0 + w16 + 15);
        if (active) {
            float s[8][4];
            #pragma unroll
            for (int nf = 0; nf < 8; nf++) { s[nf][0]=0.f; s[nf][1]=0.f; s[nf][2]=0.f; s[nf][3]=0.f; }
            {
                uint32_t ka = sb + FW_K + cur * KVS + lmo;
                #pragma unroll
                for (int kf = 0; kf < 4; kf++) {
                    #pragma unroll
                    for (int np = 0; np < 4; np++) {
                        uint32_t bk[4];
                        ldsm4(bk, ka + (uint32_t)(np * 16 * 72) * 2 + kf * 32);
                        uint32_t b0[2] = { bk[0], bk[2] };
                        uint32_t b1[2] = { bk[1], bk[3] };
                        mma16816(s[2*np],   aq[kf], b0);
                        mma16816(s[2*np+1], aq[kf], b1);
                    }
                }
            }

            if (kb >= 2 * qb) {
                #pragma unroll
                for (int nf = 0; nf < 8; nf++) {
                    int c = kb * 64 + nf * 8 + cc0;
                    if (c     > rq0)     s[nf][0] = -1e30f;
                    if (c + 1 > rq0)     s[nf][1] = -1e30f;
                    if (c     > rq0 + 8) s[nf][2] = -1e30f;
                    if (c + 1 > rq0 + 8) s[nf][3] = -1e30f;
                }
            }

            float mx0 = -1e30f, mx1 = -1e30f;
            #pragma unroll
            for (int nf = 0; nf < 8; nf++) {
                mx0 = fmaxf(mx0, fmaxf(s[nf][0], s[nf][1]));
                mx1 = fmaxf(mx1, fmaxf(s[nf][2], s[nf][3]));
            }
            mx0 = fmaxf(mx0, __shfl_xor_sync(0xffffffffu, mx0, 1));
            mx0 = fmaxf(mx0, __shfl_xor_sync(0xffffffffu, mx0, 2));
            mx1 = fmaxf(mx1, __shfl_xor_sync(0xffffffffu, mx1, 1));
            mx1 = fmaxf(mx1, __shfl_xor_sync(0xffffffffu, mx1, 2));
            float mn0 = fmaxf(m0, mx0), mn1 = fmaxf(m1, mx1);

            uint32_t pa[4][4];
            float sum0 = 0.f, sum1 = 0.f;
            #pragma unroll
            for (int np = 0; np < 4; np++) {
                float p00 = exp2f(s[2*np][0]   - mn0), p01 = exp2f(s[2*np][1]   - mn0);
                float p02 = exp2f(s[2*np][2]   - mn1), p03 = exp2f(s[2*np][3]   - mn1);
                float p10 = exp2f(s[2*np+1][0] - mn0), p11 = exp2f(s[2*np+1][1] - mn0);
                float p12 = exp2f(s[2*np+1][2] - mn1), p13 = exp2f(s[2*np+1][3] - mn1);
                sum0 += p00 + p01 + p10 + p11;
                sum1 += p02 + p03 + p12 + p13;
                pa[np][0] = h2u(p00, p01);
                pa[np][1] = h2u(p02, p03);
                pa[np][2] = h2u(p10, p11);
                pa[np][3] = h2u(p12, p13);
            }
            sum0 += __shfl_xor_sync(0xffffffffu, sum0, 1);
            sum0 += __shfl_xor_sync(0xffffffffu, sum0, 2);
            sum1 += __shfl_xor_sync(0xffffffffu, sum1, 1);
            sum1 += __shfl_xor_sync(0xffffffffu, sum1, 2);

            const bool moved = (mn0 > m0) | (mn1 > m1);
            if (__any_sync(0xffffffffu, moved)) {
                float c0 = exp2f(m0 - mn0), c1 = exp2f(m1 - mn1);
                l0 = l0 * c0 + sum0;
                l1 = l1 * c1 + sum1;
                #pragma unroll
                for (int nf = 0; nf < 8; nf++) {
                    o[nf][0] *= c0; o[nf][1] *= c0; o[nf][2] *= c1; o[nf][3] *= c1;
                }
            } else {
                l0 += sum0;
                l1 += sum1;
            }
            m0 = mn0; m1 = mn1;

            {
                uint32_t va = sb + FW_V + cur * KVS + lmo;
                #pragma unroll
                for (int kf = 0; kf < 4; kf++) {
                    #pragma unroll
                    for (int np = 0; np < 4; np++) {
                        uint32_t bv[4];
                        ldsm4t(bv, va + (uint32_t)(kf * 16 * 72) * 2 + np * 32);
                        uint32_t b0[2] = { bv[0], bv[1] };
                        uint32_t b1[2] = { bv[2], bv[3] };
                        mma16816(o[2*np],   pa[kf], b0);
                        mma16816(o[2*np+1], pa[kf], b1);
                    }
                }
            }
        }
    }

    {
        float il0 = 1.f / l0, il1 = 1.f / l1;
        __half* Og  = g_Ath + ((size_t)b * S_ + rq0) * D_ + h * DK_ + cc0;
        __half* Og8 = Og + 8 * D_;
        #pragma unroll
        for (int nf = 0; nf < 8; nf++) {
            *(__half2*)(Og  + nf * 8) = __floats2half2_rn(o[nf][0] * il0, o[nf][1] * il0);
            *(__half2*)(Og8 + nf * 8) = __floats2half2_rn(o[nf][2] * il1, o[nf][3] * il1);
        }
    }
}

// ---------------------------------------------------------------------------
// Host launcher
// ---------------------------------------------------------------------------
extern "C" void kernel_launch(void* const* d_in, const int* in_sizes, int n_in,
                              void* d_out, int out_size)
{
    const float* q  = (const float*)d_in[0];
    const float* k  = (const float*)d_in[1];
    const float* v  = (const float*)d_in[2];
    const float* Wq = (const float*)d_in[4];
    const float* bq = (const float*)d_in[5];
    const float* Wk = (const float*)d_in[6];
    const float* bk = (const float*)d_in[7];
    const float* Wv = (const float*)d_in[8];
    const float* bv = (const float*)d_in[9];
    const float* Wo = (const float*)d_in[10];
    const float* bo = (const float*)d_in[11];
    float* out = (float*)d_out;

    prep_kernel<<<4096 + 256 + 4096, 256>>>(q, k, v, Wq, Wk, Wv, Wo);

    size_t gsmem = 3 * GSTAGE_B;                // 110592 B
    cudaFuncSetAttribute(qkv_kernel,   cudaFuncAttributeMaxDynamicSharedMemorySize, (int)gsmem);
    cudaFuncSetAttribute(oproj_kernel, cudaFuncAttributeMaxDynamicSharedMemorySize, (int)gsmem);
    qkv_kernel<<<dim3(8, 32, 3), 256, gsmem>>>(bq, bk, bv);

    size_t fsmem = FW_TOT;                      // 73728 B
    cudaFuncSetAttribute(flash_kernel, cudaFuncAttributeMaxDynamicSharedMemorySize, (int)fsmem);
    flash_kernel<<<512, 256, fsmem>>>();

    oproj_kernel<<<dim3(8, 32), 256, gsmem>>>(bo, out);
}